// round 13
// baseline (speedup 1.0000x reference)
#include <cuda_runtime.h>
#include <cuda_bf16.h>

// CRF NLL: out = -(sum_b (score_b - partition_b)),  B=512, S=1024, T=32.
//
// Linear-domain forward recurrence with power-of-2 rescaling:
//   alpha_s = D(e_s) M^T alpha_{s-1},  M = exp(trans), tracked as p * 2^off.
// The 32x32 matvec is done entirely with register shuffles (lane i holds p_i;
// __shfl broadcast replaces the STS/__syncwarp/LDS round-trip of R7).
// Per-step scale 2^-k, k = exponent of one-step-stale A_0 (off the chain).
// One log at the end. 1 warp == 1 batch; 128 CTAs x 4 warps = 1 warp/SMSP.
// tags buffer is int32 on device (JAX x64-disabled downcast of jnp.int64).

#define BB 512
#define SS 1024
#define TT 32
#define PD 4
#define LN2F 0.6931471805599453f

__device__ float    g_partial[BB];
__device__ unsigned g_ctr = 0;

__device__ __forceinline__ float warp_sum(float v) {
#pragma unroll
    for (int o = 16; o; o >>= 1) v += __shfl_xor_sync(0xFFFFFFFFu, v, o);
    return v;
}

__global__ void __launch_bounds__(128, 1) crf_main(
    const float* __restrict__ em, const int* __restrict__ tags,
    const float* __restrict__ mask, const float* __restrict__ trans,
    const float* __restrict__ startt, const float* __restrict__ endt,
    float* __restrict__ out)
{
    const int w    = threadIdx.x >> 5;
    const int lane = threadIdx.x & 31;
    const int b    = blockIdx.x * 4 + w;          // one warp == one batch
    const size_t embase = (size_t)b * SS * TT;

    // Mcol[i] = exp(trans[i][lane])  (coalesced load)
    float Mcol[TT];
#pragma unroll
    for (int i = 0; i < TT; i++) Mcol[i] = __expf(trans[i * TT + lane]);

    // Prefetch pipelines (PD steps deep). Step n -> sequence index si = 1+n.
    float em_pf[PD], m_pf[PD];
#pragma unroll
    for (int u = 0; u < PD; u++) {
        em_pf[u] = em[embase + (size_t)(1 + u) * TT + lane];
        m_pf[u]  = mask[b * SS + 1 + u];
    }

    float p  = __expf(startt[lane] + em[embase + lane]);  // alpha0 (linear)
    float ex = __expf(em_pf[0]);
    float av = 1.0f;
    int offset = 0;

    // Steps 0..1023; step 1023 (si = 1024) is a dummy with mask forced to 0.
#pragma unroll 1
    for (int n0 = 0; n0 < SS; n0 += PD) {
#pragma unroll
        for (int u = 0; u < PD; u++) {
            const int n = n0 + u;

            // Stale-exponent rescale (pure ALU, off the chain)
            unsigned eb  = (__float_as_uint(av) >> 23) & 0xFFu;
            int      k   = (int)eb - 127;
            float scalef = __uint_as_float((254u - eb) << 23);   // 2^-k
            float emsc   = ex * scalef;
            float m      = m_pf[u];

            // Prefetch step n+PD into slot u (si = 1+n+PD; guard the tail)
            {
                int sn = 1 + n + PD;
                bool ok = sn < SS;
                em_pf[u] = ok ? em[embase + (size_t)sn * TT + lane] : 0.f;
                m_pf[u]  = ok ? mask[b * SS + sn] : 0.f;
            }

            // Matvec via shfl broadcast: A_lane = sum_i p_i * Mcol[i]
            float acc[8];
#pragma unroll
            for (int g = 0; g < 8; g++) {
                float s0 = __shfl_sync(0xFFFFFFFFu, p, 4 * g + 0);
                float s1 = __shfl_sync(0xFFFFFFFFu, p, 4 * g + 1);
                float s2 = __shfl_sync(0xFFFFFFFFu, p, 4 * g + 2);
                float s3 = __shfl_sync(0xFFFFFFFFu, p, 4 * g + 3);
                acc[g] = fmaf(s0, Mcol[4 * g + 0],
                         fmaf(s1, Mcol[4 * g + 1],
                         fmaf(s2, Mcol[4 * g + 2], s3 * Mcol[4 * g + 3])));
            }
            float A = ((acc[0] + acc[1]) + (acc[2] + acc[3]))
                    + ((acc[4] + acc[5]) + (acc[6] + acc[7]));

            float avn = __shfl_sync(0xFFFFFFFFu, A, 0);  // next step's scale src
            float pn  = A * emsc;
            bool upd  = (m != 0.f);
            p = upd ? pn : p;
            offset += upd ? k : 0;
            av = avn;
            ex = __expf(em_pf[(u + 1) & (PD - 1)]);   // next step's exp (off chain)
        }
    }

    // partition_b = ln(sum_j p_j * exp(end_j)) + offset * ln2
    float val = warp_sum(p * __expf(endt[lane]));
    float partition = logf(val) + (float)offset * LN2F;

    // ---- gold-path score, lanes strided over sequence positions ----
    float sc = 0.f, ms = 0.f;
    const int* tg = tags + (size_t)b * SS;
#pragma unroll 4
    for (int it = 0; it < SS / 32; it++) {
        int s  = it * 32 + lane;
        int tc = tg[s];
        float mm = mask[b * SS + s];
        ms += mm;
        if (s == 0) {
            sc += startt[tc] + em[embase + tc];
        } else {
            int tp = tg[s - 1];
            sc += (em[embase + (size_t)s * TT + tc] + trans[tp * TT + tc]) * mm;
        }
    }
    sc = warp_sum(sc); ms = warp_sum(ms);

    if (lane == 0) {
        int last = (int)ms - 1;
        g_partial[b] = (sc + endt[tg[last]]) - partition;
        __threadfence();
    }
    __syncthreads();

    // ---- last-CTA-done final reduction (no separate kernel) ----
    if (w == 0) {
        unsigned done = 0;
        if (lane == 0) done = atomicAdd(&g_ctr, 1);
        done = __shfl_sync(0xFFFFFFFFu, done, 0);
        if (done == gridDim.x - 1) {
            __threadfence();
            float v = 0.f;
#pragma unroll
            for (int i = 0; i < BB / 32; i++) v += g_partial[lane + i * 32];
            v = warp_sum(v);
            if (lane == 0) { out[0] = -v; g_ctr = 0; }   // reset for graph replay
        }
    }
}

extern "C" void kernel_launch(void* const* d_in, const int* in_sizes, int n_in,
                              void* d_out, int out_size) {
    const float* em    = (const float*)d_in[0];
    const int*   tags  = (const int*)d_in[1];
    const float* mask  = (const float*)d_in[2];
    const float* trans = (const float*)d_in[3];
    const float* st    = (const float*)d_in[4];
    const float* en    = (const float*)d_in[5];
    (void)in_sizes; (void)n_in; (void)out_size;

    crf_main<<<BB / 4, 128>>>(em, tags, mask, trans, st, en, (float*)d_out);
}

// round 15
// speedup vs baseline: 1.4977x; 1.4977x over previous
#include <cuda_runtime.h>
#include <cuda_bf16.h>

// CRF NLL: out = -(sum_b (score_b - partition_b)),  B=512, S=1024, T=32.
//
// Linear-domain forward recurrence with power-of-2 rescaling (R7 structure):
//   alpha_s = D(e_s) M^T alpha_{s-1}, M = exp(trans), tracked as p * 2^off.
// Matvec: lane j stores p_j to smem, all lanes read back via LDS.128
// broadcast. The __syncwarp of R7 is REMOVED: same-warp smem ops are
// processed by the LSU in program order and the loop body is branch-free
// (warp never diverges); asm volatile pins the compiler ordering.
// Per-step scale 2^-k, k = exponent of one-step-stale A_0 (off the chain).
// tags buffer is int32 on device (JAX x64-disabled downcast of jnp.int64).

#define BB 512
#define SS 1024
#define TT 32
#define PD 8
#define LN2F 0.6931471805599453f

__device__ float    g_partial[BB];
__device__ unsigned g_ctr = 0;

__device__ __forceinline__ float warp_sum(float v) {
#pragma unroll
    for (int o = 16; o; o >>= 1) v += __shfl_xor_sync(0xFFFFFFFFu, v, o);
    return v;
}

__device__ __forceinline__ void sts_f32(unsigned addr, float v) {
    asm volatile("st.shared.b32 [%0], %1;" :: "r"(addr), "f"(v) : "memory");
}
__device__ __forceinline__ float4 lds_f128(unsigned addr) {
    float4 r;
    asm volatile("ld.shared.v4.f32 {%0,%1,%2,%3}, [%4];"
                 : "=f"(r.x), "=f"(r.y), "=f"(r.z), "=f"(r.w) : "r"(addr));
    return r;
}

__global__ void __launch_bounds__(128, 1) crf_main(
    const float* __restrict__ em, const int* __restrict__ tags,
    const float* __restrict__ mask, const float* __restrict__ trans,
    const float* __restrict__ startt, const float* __restrict__ endt,
    float* __restrict__ out)
{
    __shared__ __align__(16) float sp[4][2][TT];   // per-warp ping-pong state
    const int w    = threadIdx.x >> 5;
    const int lane = threadIdx.x & 31;
    const int b    = blockIdx.x * 4 + w;           // one warp == one batch
    const size_t embase = (size_t)b * SS * TT;

    const unsigned sbase =
        (unsigned)__cvta_generic_to_shared(&sp[w][0][0]);   // +128 = buffer 1

    // Mcol[i] = exp(trans[i][lane])  (coalesced load)
    float Mcol[TT];
#pragma unroll
    for (int i = 0; i < TT; i++) Mcol[i] = __expf(trans[i * TT + lane]);

    // Prefetch pipelines (PD steps deep). Step n -> sequence index si = 1+n.
    float em_pf[PD], m_pf[PD];
#pragma unroll
    for (int u = 0; u < PD; u++) {
        em_pf[u] = em[embase + (size_t)(1 + u) * TT + lane];
        m_pf[u]  = mask[b * SS + 1 + u];
    }

    float p  = __expf(startt[lane] + em[embase + lane]);  // alpha0 (linear)
    float ex = __expf(em_pf[0]);
    float av = 1.0f;
    int offset = 0;
    unsigned wb = 0;                                      // ping-pong (0/128)

    // Steps 0..1023; step 1023 (si = 1024) is a dummy with mask forced to 0.
#pragma unroll 1
    for (int n0 = 0; n0 < SS; n0 += PD) {
#pragma unroll
        for (int u = 0; u < PD; u++) {
            const int n = n0 + u;

            // Stale-exponent rescale (pure ALU, off the chain)
            unsigned eb  = (__float_as_uint(av) >> 23) & 0xFFu;
            int      k   = (int)eb - 127;
            float scalef = __uint_as_float((254u - eb) << 23);   // 2^-k
            float emsc   = ex * scalef;
            float m      = m_pf[u];

            // Publish state, then broadcast-read (same-warp LSU order; no sync)
            sts_f32(sbase + wb + lane * 4u, p);

            // Prefetch step n+PD into slot u (si = 1+n+PD; guard the tail)
            {
                int sn = 1 + n + PD;
                bool ok = sn < SS;                        // warp-uniform
                em_pf[u] = ok ? em[embase + (size_t)sn * TT + lane] : 0.f;
                m_pf[u]  = ok ? mask[b * SS + sn] : 0.f;
            }

            // Matvec: A_lane = sum_i p_i * Mcol[i]  (8x LDS.128 broadcast)
            float acc[8];
#pragma unroll
            for (int g = 0; g < 8; g++) {
                float4 v = lds_f128(sbase + wb + g * 16u);
                acc[g] = fmaf(v.x, Mcol[4 * g + 0],
                         fmaf(v.y, Mcol[4 * g + 1],
                         fmaf(v.z, Mcol[4 * g + 2], v.w * Mcol[4 * g + 3])));
            }
            float A = ((acc[0] + acc[1]) + (acc[2] + acc[3]))
                    + ((acc[4] + acc[5]) + (acc[6] + acc[7]));

            float avn = __shfl_sync(0xFFFFFFFFu, A, 0);  // next step's scale src
            float pn  = A * emsc;
            bool upd  = (m != 0.f);
            p = upd ? pn : p;
            offset += upd ? k : 0;
            av = avn;
            wb ^= 128u;
            ex = __expf(em_pf[(u + 1) & (PD - 1)]);  // next step's exp (off chain)
        }
    }

    // partition_b = ln(sum_j p_j * exp(end_j)) + offset * ln2
    float val = warp_sum(p * __expf(endt[lane]));
    float partition = logf(val) + (float)offset * LN2F;

    // ---- gold-path score, lanes strided over sequence positions ----
    float sc = 0.f, ms = 0.f;
    const int* tg = tags + (size_t)b * SS;
#pragma unroll 4
    for (int it = 0; it < SS / 32; it++) {
        int s  = it * 32 + lane;
        int tc = tg[s];
        float mm = mask[b * SS + s];
        ms += mm;
        if (s == 0) {
            sc += startt[tc] + em[embase + tc];
        } else {
            int tp = tg[s - 1];
            sc += (em[embase + (size_t)s * TT + tc] + trans[tp * TT + tc]) * mm;
        }
    }
    sc = warp_sum(sc); ms = warp_sum(ms);

    if (lane == 0) {
        int last = (int)ms - 1;
        g_partial[b] = (sc + endt[tg[last]]) - partition;
        __threadfence();
    }
    __syncthreads();

    // ---- last-CTA-done final reduction (no separate kernel) ----
    if (w == 0) {
        unsigned done = 0;
        if (lane == 0) done = atomicAdd(&g_ctr, 1);
        done = __shfl_sync(0xFFFFFFFFu, done, 0);
        if (done == gridDim.x - 1) {
            __threadfence();
            float v = 0.f;
#pragma unroll
            for (int i = 0; i < BB / 32; i++) v += g_partial[lane + i * 32];
            v = warp_sum(v);
            if (lane == 0) { out[0] = -v; g_ctr = 0; }   // reset for graph replay
        }
    }
}

extern "C" void kernel_launch(void* const* d_in, const int* in_sizes, int n_in,
                              void* d_out, int out_size) {
    const float* em    = (const float*)d_in[0];
    const int*   tags  = (const int*)d_in[1];
    const float* mask  = (const float*)d_in[2];
    const float* trans = (const float*)d_in[3];
    const float* st    = (const float*)d_in[4];
    const float* en    = (const float*)d_in[5];
    (void)in_sizes; (void)n_in; (void)out_size;

    crf_main<<<BB / 4, 128>>>(em, tags, mask, trans, st, en, (float*)d_out);
}